// round 10
// baseline (speedup 1.0000x reference)
#include <cuda_runtime.h>
#include <math.h>
#include <stdint.h>

// Problem constants
// x: [8, 512, 32, 32]  -> [8, 512, 1024]
// heads = 8, cph = 64, groups = 32 (16 ch/group), eps = 1e-5

// ---------------------------------------------------------------------------
// Scratch (device globals; no dynamic allocation allowed)
// ---------------------------------------------------------------------------
__device__ float g_xn [8 * 512 * 1024];        // GroupNorm output           16 MB
__device__ float g_qkv[8 * 1536 * 1024];       // QKV projection             48 MB
__device__ float g_vt [64 * 1024 * 64];        // V transposed [bh][j][c]    16 MB
__device__ float g_wv [8 * 512 * 1024];        // attention output (flat)    16 MB

// ---------------------------------------------------------------------------
// GroupNorm: one block per (group, batch). 16 ch x 1024 spatial per group.
// ---------------------------------------------------------------------------
__global__ void gn_kernel(const float* __restrict__ x,
                          const float* __restrict__ gw,
                          const float* __restrict__ gb) {
    const int g = blockIdx.x;   // 0..31
    const int n = blockIdx.y;   // 0..7
    const float* xp = x + ((size_t)n * 512 + (size_t)g * 16) * 1024;

    float s = 0.f, s2 = 0.f;
    for (int i = threadIdx.x; i < 16384; i += 256) {
        float v = xp[i];
        s += v; s2 += v * v;
    }
    __shared__ float rs[8], rs2[8];
#pragma unroll
    for (int o = 16; o; o >>= 1) {
        s  += __shfl_xor_sync(0xffffffffu, s,  o);
        s2 += __shfl_xor_sync(0xffffffffu, s2, o);
    }
    const int wid = threadIdx.x >> 5, lane = threadIdx.x & 31;
    if (lane == 0) { rs[wid] = s; rs2[wid] = s2; }
    __syncthreads();
    if (threadIdx.x < 32) {
        s  = (threadIdx.x < 8) ? rs [threadIdx.x] : 0.f;
        s2 = (threadIdx.x < 8) ? rs2[threadIdx.x] : 0.f;
#pragma unroll
        for (int o = 4; o; o >>= 1) {
            s  += __shfl_xor_sync(0xffffffffu, s,  o);
            s2 += __shfl_xor_sync(0xffffffffu, s2, o);
        }
        if (threadIdx.x == 0) { rs[0] = s; rs2[0] = s2; }
    }
    __syncthreads();
    const float mean = rs[0] * (1.f / 16384.f);
    const float var  = rs2[0] * (1.f / 16384.f) - mean * mean;
    const float rstd = rsqrtf(var + 1e-5f);

    float* op = g_xn + ((size_t)n * 512 + (size_t)g * 16) * 1024;
    for (int i = threadIdx.x; i < 16384; i += 256) {
        const int ch = g * 16 + (i >> 10);
        op[i] = (xp[i] - mean) * rstd * gw[ch] + gb[ch];
    }
}

// ---------------------------------------------------------------------------
// Batched SGEMM: Y[n] = W[M,K] @ X[n][K,1024] + bias
// block 256, 64x64 output tile, 4x4 per thread, K-tiles of 16.
// grid: (1024/64, M/64, batch)
// ---------------------------------------------------------------------------
template <int KDIM>
__global__ __launch_bounds__(256)
void gemm_bias_kernel(const float* __restrict__ W,
                      const float* __restrict__ bias,
                      const float* __restrict__ X,
                      float* __restrict__ Y,
                      int M) {
    const int n0 = blockIdx.x * 64;
    const int m0 = blockIdx.y * 64;
    const int nb = blockIdx.z;
    const float* Xb = X + (size_t)nb * KDIM * 1024;
    float* Yb = Y + (size_t)nb * M * 1024;

    __shared__ float As[16 * 68];   // [k][m], padded row (16B-aligned rows)
    __shared__ float Bs[16 * 64];   // [k][n]

    const int tid = threadIdx.x;
    const int tx = tid & 15;        // output column group
    const int ty = tid >> 4;        // output row group

    // loader indices
    const int am = tid >> 2;             // 0..63 (row m within tile)
    const int ak = (tid & 3) * 4;        // 0,4,8,12 (k offset, float4)
    const int bk = tid >> 4;             // 0..15 (k within tile)
    const int bn = (tid & 15) * 4;       // column offset, float4

    float acc[4][4] = {};

    for (int k0 = 0; k0 < KDIM; k0 += 16) {
        const float4 a = *(const float4*)&W [(size_t)(m0 + am) * KDIM + k0 + ak];
        const float4 b = *(const float4*)&Xb[(size_t)(k0 + bk) * 1024 + n0 + bn];
        __syncthreads();
        As[(ak + 0) * 68 + am] = a.x;
        As[(ak + 1) * 68 + am] = a.y;
        As[(ak + 2) * 68 + am] = a.z;
        As[(ak + 3) * 68 + am] = a.w;
        *(float4*)&Bs[bk * 64 + bn] = b;
        __syncthreads();
#pragma unroll
        for (int kk = 0; kk < 16; kk++) {
            const float4 av = *(const float4*)&As[kk * 68 + ty * 4];
            const float4 bv = *(const float4*)&Bs[kk * 64 + tx * 4];
            const float ar[4] = {av.x, av.y, av.z, av.w};
            const float br[4] = {bv.x, bv.y, bv.z, bv.w};
#pragma unroll
            for (int i = 0; i < 4; i++)
#pragma unroll
                for (int j = 0; j < 4; j++)
                    acc[i][j] = fmaf(ar[i], br[j], acc[i][j]);
        }
    }

#pragma unroll
    for (int i = 0; i < 4; i++) {
        const int row = m0 + ty * 4 + i;
        const float bv = bias[row];
        float4 o = make_float4(acc[i][0] + bv, acc[i][1] + bv,
                               acc[i][2] + bv, acc[i][3] + bv);
        *(float4*)&Yb[(size_t)row * 1024 + n0 + tx * 4] = o;
    }
}

// ---------------------------------------------------------------------------
// V transpose: v[n][1024 + head*64 + c][j]  ->  vt[bh][j][c]
// 32x32 smem tiles. grid (32 j-tiles, 2 c-tiles, 64 bh), block (32, 8)
// ---------------------------------------------------------------------------
__global__ void vtrans_kernel() {
    __shared__ float t[32][33];
    const int bh = blockIdx.z;
    const int n = bh >> 3, head = bh & 7;
    const float* v = g_qkv + ((size_t)n * 1536 + 1024 + (size_t)head * 64) * 1024;
    const int j0 = blockIdx.x * 32;
    const int c0 = blockIdx.y * 32;

    for (int r = threadIdx.y; r < 32; r += 8)
        t[r][threadIdx.x] = v[(size_t)(c0 + r) * 1024 + j0 + threadIdx.x];
    __syncthreads();
    float* o = g_vt + ((size_t)bh * 1024 + j0) * 64 + c0;
    for (int r = threadIdx.y; r < 32; r += 8)
        o[(size_t)r * 64 + threadIdx.x] = t[threadIdx.x][r];
}

// ---------------------------------------------------------------------------
// Flash attention: seq = 1024, d = 64.
// grid (16 i-tiles, 64 bh), block 256. Each block: 64 query rows.
// S[i,j] = sum_c q[c,i]*k[c,j] * 0.125 (scale folded into Q load).
// Online softmax; PV via smem-staged P and transposed V.
// Output written in the torch-faithful flat layout:
//   wv[n][head*65536 + i*64 + c]
// ---------------------------------------------------------------------------
__global__ __launch_bounds__(256)
void attn_kernel() {
    extern __shared__ float sm[];
    float* Qs = sm;            // [c][i]  64x64
    float* Ks = sm + 4096;     // [c][j]  64x64
    float* Vs = sm + 8192;     // [j][c]  64x64
    float* Ps = sm + 12288;    // [i][j]  64 rows, stride 68

    const int tid = threadIdx.x;
    const int tx = tid & 15;    // j / c column group
    const int ty = tid >> 4;    // i row group
    const int bh = blockIdx.y;
    const int n = bh >> 3, head = bh & 7;
    const int i0 = blockIdx.x * 64;

    const float* q   = g_qkv + ((size_t)n * 1536 + (size_t)head * 64) * 1024;
    const float* k   = q + (size_t)512 * 1024;
    const float* vtb = g_vt + (size_t)bh * 1024 * 64;

    // Load Q tile (scaled): Qs[c][i] = q[c][i0+i] * 0.125
    {
        const int i4 = (tid & 15) * 4;
        const int c0 = tid >> 4;
        for (int c = c0; c < 64; c += 16) {
            float4 qa = *(const float4*)&q[(size_t)c * 1024 + i0 + i4];
            qa.x *= 0.125f; qa.y *= 0.125f; qa.z *= 0.125f; qa.w *= 0.125f;
            *(float4*)&Qs[c * 64 + i4] = qa;
        }
    }

    float O[4][4] = {};
    float mrow[4] = {-1e30f, -1e30f, -1e30f, -1e30f};
    float lrow[4] = {};

    for (int jt = 0; jt < 16; jt++) {
        const int j0 = jt * 64;
        // Load K tile [c][j] and V tile [j][c]
        {
            const int x4 = (tid & 15) * 4;
            const int r0 = tid >> 4;
            __syncthreads();   // prior PV reads of Vs/Ps done; Q writes visible
            for (int r = r0; r < 64; r += 16) {
                *(float4*)&Ks[r * 64 + x4] =
                    *(const float4*)&k[(size_t)r * 1024 + j0 + x4];
                *(float4*)&Vs[r * 64 + x4] =
                    *(const float4*)&vtb[(size_t)(j0 + r) * 64 + x4];
            }
            __syncthreads();
        }

        // S = (Q*scale)^T K  (4x4 per thread)
        float S[4][4] = {};
#pragma unroll 8
        for (int c = 0; c < 64; c++) {
            const float4 qa = *(const float4*)&Qs[c * 64 + ty * 4];
            const float4 kb = *(const float4*)&Ks[c * 64 + tx * 4];
            const float qr[4] = {qa.x, qa.y, qa.z, qa.w};
            const float kr[4] = {kb.x, kb.y, kb.z, kb.w};
#pragma unroll
            for (int i = 0; i < 4; i++)
#pragma unroll
                for (int j = 0; j < 4; j++)
                    S[i][j] = fmaf(qr[i], kr[j], S[i][j]);
        }

        // Online softmax per row (row owned by 16 consecutive lanes)
#pragma unroll
        for (int i = 0; i < 4; i++) {
            float tmax = fmaxf(fmaxf(S[i][0], S[i][1]), fmaxf(S[i][2], S[i][3]));
#pragma unroll
            for (int o = 1; o < 16; o <<= 1)
                tmax = fmaxf(tmax, __shfl_xor_sync(0xffffffffu, tmax, o));
            const float mnew = fmaxf(mrow[i], tmax);
            const float corr = __expf(mrow[i] - mnew);
            mrow[i] = mnew;
            float p[4], ps = 0.f;
#pragma unroll
            for (int j = 0; j < 4; j++) { p[j] = __expf(S[i][j] - mnew); ps += p[j]; }
#pragma unroll
            for (int o = 1; o < 16; o <<= 1)
                ps += __shfl_xor_sync(0xffffffffu, ps, o);
            lrow[i] = lrow[i] * corr + ps;
#pragma unroll
            for (int j = 0; j < 4; j++) O[i][j] *= corr;
            *(float4*)&Ps[(ty * 4 + i) * 68 + tx * 4] =
                make_float4(p[0], p[1], p[2], p[3]);
        }
        __syncthreads();

        // O += P @ V   (O[i][c] += sum_j P[i,j] * Vs[j][c])
#pragma unroll 8
        for (int j = 0; j < 64; j++) {
            const float4 vv = *(const float4*)&Vs[j * 64 + tx * 4];
            const float vr[4] = {vv.x, vv.y, vv.z, vv.w};
#pragma unroll
            for (int i = 0; i < 4; i++) {
                const float pv = Ps[(ty * 4 + i) * 68 + j];
#pragma unroll
                for (int jj = 0; jj < 4; jj++)
                    O[i][jj] = fmaf(pv, vr[jj], O[i][jj]);
            }
        }
    }

    // Epilogue: normalize and store in flat (torch-reshape-faithful) layout.
    float* wb = g_wv + (size_t)n * 524288 + (size_t)head * 65536;
#pragma unroll
    for (int i = 0; i < 4; i++) {
        const float inv = 1.f / lrow[i];
        const int row = i0 + ty * 4 + i;
        float4 o = make_float4(O[i][0] * inv, O[i][1] * inv,
                               O[i][2] * inv, O[i][3] * inv);
        *(float4*)&wb[(size_t)row * 64 + tx * 4] = o;
    }
}

// ---------------------------------------------------------------------------
// Launch
// ---------------------------------------------------------------------------
extern "C" void kernel_launch(void* const* d_in, const int* in_sizes, int n_in,
                              void* d_out, int out_size) {
    const float* x     = (const float*)d_in[0];
    const float* gw    = (const float*)d_in[1];
    const float* gb    = (const float*)d_in[2];
    const float* qkv_w = (const float*)d_in[3];
    const float* qkv_b = (const float*)d_in[4];
    const float* out_w = (const float*)d_in[5];
    const float* out_b = (const float*)d_in[6];
    float* out = (float*)d_out;

    float *xn_p, *qkv_p, *wv_p;
    cudaGetSymbolAddress((void**)&xn_p,  g_xn);
    cudaGetSymbolAddress((void**)&qkv_p, g_qkv);
    cudaGetSymbolAddress((void**)&wv_p,  g_wv);

    // attention kernel needs 66560 B of dynamic smem
    cudaFuncSetAttribute(attn_kernel,
                         cudaFuncAttributeMaxDynamicSharedMemorySize, 66560);

    // 1. GroupNorm
    gn_kernel<<<dim3(32, 8), 256>>>(x, gw, gb);

    // 2. QKV projection: [1536,512] @ [512,1024] per batch
    gemm_bias_kernel<512><<<dim3(16, 24, 8), 256>>>(qkv_w, qkv_b, xn_p, qkv_p, 1536);

    // 3. V transpose for the PV GEMM
    vtrans_kernel<<<dim3(32, 2, 64), dim3(32, 8)>>>();

    // 4. Flash attention
    attn_kernel<<<dim3(16, 64), 256, 66560>>>();

    // 5. Output projection: [512,512] @ [512,1024] per batch -> d_out
    gemm_bias_kernel<512><<<dim3(16, 8, 8), 256>>>(out_w, out_b, wv_p, out, 512);
}

// round 12
// speedup vs baseline: 1.4548x; 1.4548x over previous
#include <cuda_runtime.h>
#include <math.h>
#include <stdint.h>

// x: [8, 512, 32, 32] -> [8, 512, 1024]; heads=8, cph=64, groups=32, eps=1e-5

// ---------------------------------------------------------------------------
// Scratch (device globals; no dynamic allocation allowed)
// ---------------------------------------------------------------------------
__device__ float g_xn  [8 * 512 * 1024];       // GroupNorm output            16 MB
__device__ float g_qkv [8 * 1536 * 1024];      // QKV projection              48 MB
__device__ float g_vt  [64 * 1024 * 64];       // V transposed [bh][j][c]     16 MB
__device__ float g_wv  [8 * 512 * 1024];       // attention out (flat view)   16 MB

__device__ __forceinline__ float to_tf32(float x) {
    float y; asm("cvt.rna.tf32.f32 %0, %1;" : "=f"(y) : "f"(x)); return y;
}
__device__ __forceinline__ void mma_tf32_16x8x8(
    float& d0, float& d1, float& d2, float& d3,
    uint32_t a0, uint32_t a1, uint32_t a2, uint32_t a3,
    uint32_t b0, uint32_t b1) {
    asm volatile(
        "mma.sync.aligned.m16n8k8.row.col.f32.tf32.tf32.f32 "
        "{%0,%1,%2,%3}, {%4,%5,%6,%7}, {%8,%9}, {%0,%1,%2,%3};"
        : "+f"(d0), "+f"(d1), "+f"(d2), "+f"(d3)
        : "r"(a0), "r"(a1), "r"(a2), "r"(a3), "r"(b0), "r"(b1));
}

// ---------------------------------------------------------------------------
// GroupNorm
// ---------------------------------------------------------------------------
__global__ void gn_kernel(const float* __restrict__ x,
                          const float* __restrict__ gw,
                          const float* __restrict__ gb) {
    const int g = blockIdx.x, n = blockIdx.y;
    const float* xp = x + ((size_t)n * 512 + (size_t)g * 16) * 1024;
    float s = 0.f, s2 = 0.f;
    for (int i = threadIdx.x; i < 16384; i += 256) {
        float v = xp[i]; s += v; s2 += v * v;
    }
    __shared__ float rs[8], rs2[8];
#pragma unroll
    for (int o = 16; o; o >>= 1) {
        s  += __shfl_xor_sync(0xffffffffu, s,  o);
        s2 += __shfl_xor_sync(0xffffffffu, s2, o);
    }
    const int wid = threadIdx.x >> 5, lane = threadIdx.x & 31;
    if (lane == 0) { rs[wid] = s; rs2[wid] = s2; }
    __syncthreads();
    if (threadIdx.x < 32) {
        s  = (threadIdx.x < 8) ? rs [threadIdx.x] : 0.f;
        s2 = (threadIdx.x < 8) ? rs2[threadIdx.x] : 0.f;
#pragma unroll
        for (int o = 4; o; o >>= 1) {
            s  += __shfl_xor_sync(0xffffffffu, s,  o);
            s2 += __shfl_xor_sync(0xffffffffu, s2, o);
        }
        if (threadIdx.x == 0) { rs[0] = s; rs2[0] = s2; }
    }
    __syncthreads();
    const float mean = rs[0] * (1.f / 16384.f);
    const float var  = rs2[0] * (1.f / 16384.f) - mean * mean;
    const float rstd = rsqrtf(var + 1e-5f);
    float* op = g_xn + ((size_t)n * 512 + (size_t)g * 16) * 1024;
    for (int i = threadIdx.x; i < 16384; i += 256) {
        const int ch = g * 16 + (i >> 10);
        op[i] = (xp[i] - mean) * rstd * gw[ch] + gb[ch];
    }
}

// ---------------------------------------------------------------------------
// tf32 mma.sync GEMM:  Y[nb][m][n] = sum_k W[m][k] * B[nb][k][n] + bias[m]
// 128x128 block tile, 8 warps (64x32 each), K-chunks of 32, K = 512.
// grid (1024/128, M/128, batch), block 256.
// A smem stride 36 (A-frag LDS conflict-free), B smem stride 136.
// ---------------------------------------------------------------------------
__global__ __launch_bounds__(256)
void mma_gemm(const float* __restrict__ W, const float* __restrict__ bias,
              const float* __restrict__ B, float* __restrict__ Y, int M) {
    __shared__ float As[128 * 36];   // [m][k]
    __shared__ float Bs[32 * 136];   // [k][n]

    const int tid = threadIdx.x, w = tid >> 5, lane = tid & 31;
    const int n0 = blockIdx.x * 128, m0 = blockIdx.y * 128, nb = blockIdx.z;
    const float* Bb = B + (size_t)nb * 512 * 1024;
    float* Yb = Y + (size_t)nb * M * 1024;

    const int wm = (w >> 2) * 64;        // warp m offset (0 / 64)
    const int wn = (w & 3) * 32;         // warp n offset (0/32/64/96)
    const int gid = lane >> 2;           // 0..7
    const int tig = lane & 3;            // 0..3

    float acc[4][4][4] = {};             // [mt][nt][reg]

    // gmem->reg prefetch of chunk 0
    float4 pa[4], pb[4];
#pragma unroll
    for (int v = 0; v < 4; v++) {
        const int fa = tid + 256 * v;                // A: 128 rows x 8 float4
        pa[v] = *(const float4*)&W [(size_t)(m0 + (fa >> 3)) * 512 + (fa & 7) * 4];
        const int fb = tid + 256 * v;                // B: 32 rows x 32 float4
        pb[v] = *(const float4*)&Bb[(size_t)(fb >> 5) * 1024 + n0 + (fb & 31) * 4];
    }

    for (int kc = 0; kc < 16; kc++) {
        __syncthreads();
#pragma unroll
        for (int v = 0; v < 4; v++) {
            const int fa = tid + 256 * v;
            float4 a = pa[v];
            a.x = to_tf32(a.x); a.y = to_tf32(a.y); a.z = to_tf32(a.z); a.w = to_tf32(a.w);
            *(float4*)&As[(fa >> 3) * 36 + (fa & 7) * 4] = a;
            const int fb = tid + 256 * v;
            float4 b = pb[v];
            b.x = to_tf32(b.x); b.y = to_tf32(b.y); b.z = to_tf32(b.z); b.w = to_tf32(b.w);
            *(float4*)&Bs[(fb >> 5) * 136 + (fb & 31) * 4] = b;
        }
        __syncthreads();

        if (kc < 15) {
            const int k0 = (kc + 1) * 32;
#pragma unroll
            for (int v = 0; v < 4; v++) {
                const int fa = tid + 256 * v;
                pa[v] = *(const float4*)&W [(size_t)(m0 + (fa >> 3)) * 512 + k0 + (fa & 7) * 4];
                const int fb = tid + 256 * v;
                pb[v] = *(const float4*)&Bb[(size_t)(k0 + (fb >> 5)) * 1024 + n0 + (fb & 31) * 4];
            }
        }

#pragma unroll
        for (int ks = 0; ks < 4; ks++) {
            const int kk = ks * 8;
            uint32_t af[4][4];
#pragma unroll
            for (int mt = 0; mt < 4; mt++) {
                const int r = (wm + mt * 16 + gid) * 36 + kk + tig;
                af[mt][0] = __float_as_uint(As[r]);
                af[mt][1] = __float_as_uint(As[r + 8 * 36]);
                af[mt][2] = __float_as_uint(As[r + 4]);
                af[mt][3] = __float_as_uint(As[r + 8 * 36 + 4]);
            }
            uint32_t bf[4][2];
#pragma unroll
            for (int nt = 0; nt < 4; nt++) {
                const int c = (kk + tig) * 136 + wn + nt * 8 + gid;
                bf[nt][0] = __float_as_uint(Bs[c]);
                bf[nt][1] = __float_as_uint(Bs[c + 4 * 136]);
            }
#pragma unroll
            for (int mt = 0; mt < 4; mt++)
#pragma unroll
                for (int nt = 0; nt < 4; nt++)
                    mma_tf32_16x8x8(acc[mt][nt][0], acc[mt][nt][1],
                                    acc[mt][nt][2], acc[mt][nt][3],
                                    af[mt][0], af[mt][1], af[mt][2], af[mt][3],
                                    bf[nt][0], bf[nt][1]);
        }
    }

    // Epilogue: bias + direct float2 stores
#pragma unroll
    for (int mt = 0; mt < 4; mt++) {
        const int r0 = m0 + wm + mt * 16 + gid;
        const float bv0 = bias[r0], bv1 = bias[r0 + 8];
#pragma unroll
        for (int nt = 0; nt < 4; nt++) {
            const int col = n0 + wn + nt * 8 + tig * 2;
            *(float2*)&Yb[(size_t)r0 * 1024 + col] =
                make_float2(acc[mt][nt][0] + bv0, acc[mt][nt][1] + bv0);
            *(float2*)&Yb[(size_t)(r0 + 8) * 1024 + col] =
                make_float2(acc[mt][nt][2] + bv1, acc[mt][nt][3] + bv1);
        }
    }
}

// ---------------------------------------------------------------------------
// V transpose: qkv V section [c][j] -> vt[bh][j][c]
// ---------------------------------------------------------------------------
__global__ void vtrans_kernel() {
    __shared__ float t[32][33];
    const int bh = blockIdx.z, n = bh >> 3, head = bh & 7;
    const float* v = g_qkv + ((size_t)n * 1536 + 1024 + (size_t)head * 64) * 1024;
    const int j0 = blockIdx.x * 32, c0 = blockIdx.y * 32;
    for (int r = threadIdx.y; r < 32; r += 8)
        t[r][threadIdx.x] = v[(size_t)(c0 + r) * 1024 + j0 + threadIdx.x];
    __syncthreads();
    float* o = g_vt + ((size_t)bh * 1024 + j0) * 64 + c0;
    for (int r = threadIdx.y; r < 32; r += 8)
        o[(size_t)r * 64 + threadIdx.x] = t[threadIdx.x][r];
}

// ---------------------------------------------------------------------------
// Flash attention: seq 1024, d 64. grid(16, 64), block 256, 64x64 tiles.
// ---------------------------------------------------------------------------
__global__ __launch_bounds__(256)
void attn_kernel() {
    extern __shared__ float sm[];
    float* Qs = sm;            // [c][i]  64x64
    float* Ks = sm + 4096;     // [c][j]  64x64
    float* Vs = sm + 8192;     // [j][c]  64x64
    float* Ps = sm + 12288;    // [i][j]  64 rows, stride 68

    const int tid = threadIdx.x;
    const int tx = tid & 15, ty = tid >> 4;
    const int bh = blockIdx.y, n = bh >> 3, head = bh & 7;
    const int i0 = blockIdx.x * 64;

    const float* q   = g_qkv + ((size_t)n * 1536 + (size_t)head * 64) * 1024;
    const float* k   = q + (size_t)512 * 1024;
    const float* vtb = g_vt + (size_t)bh * 1024 * 64;

    {   // Q tile (scaled)
        const int i4 = (tid & 15) * 4, c0 = tid >> 4;
        for (int c = c0; c < 64; c += 16) {
            float4 qa = *(const float4*)&q[(size_t)c * 1024 + i0 + i4];
            qa.x *= 0.125f; qa.y *= 0.125f; qa.z *= 0.125f; qa.w *= 0.125f;
            *(float4*)&Qs[c * 64 + i4] = qa;
        }
    }

    float O[4][4] = {};
    float mrow[4] = {-1e30f, -1e30f, -1e30f, -1e30f};
    float lrow[4] = {};

    for (int jt = 0; jt < 16; jt++) {
        const int j0 = jt * 64;
        {
            const int x4 = (tid & 15) * 4, r0 = tid >> 4;
            __syncthreads();
            for (int r = r0; r < 64; r += 16) {
                *(float4*)&Ks[r * 64 + x4] =
                    *(const float4*)&k[(size_t)r * 1024 + j0 + x4];
                *(float4*)&Vs[r * 64 + x4] =
                    *(const float4*)&vtb[(size_t)(j0 + r) * 64 + x4];
            }
            __syncthreads();
        }

        float S[4][4] = {};
#pragma unroll 8
        for (int c = 0; c < 64; c++) {
            const float4 qa = *(const float4*)&Qs[c * 64 + ty * 4];
            const float4 kb = *(const float4*)&Ks[c * 64 + tx * 4];
            const float qr[4] = {qa.x, qa.y, qa.z, qa.w};
            const float kr[4] = {kb.x, kb.y, kb.z, kb.w};
#pragma unroll
            for (int i = 0; i < 4; i++)
#pragma unroll
                for (int j = 0; j < 4; j++)
                    S[i][j] = fmaf(qr[i], kr[j], S[i][j]);
        }

#pragma unroll
        for (int i = 0; i < 4; i++) {
            float tmax = fmaxf(fmaxf(S[i][0], S[i][1]), fmaxf(S[i][2], S[i][3]));
#pragma unroll
            for (int o = 1; o < 16; o <<= 1)
                tmax = fmaxf(tmax, __shfl_xor_sync(0xffffffffu, tmax, o));
            const float mnew = fmaxf(mrow[i], tmax);
            const float corr = __expf(mrow[i] - mnew);
            mrow[i] = mnew;
            float p[4], ps = 0.f;
#pragma unroll
            for (int j = 0; j < 4; j++) { p[j] = __expf(S[i][j] - mnew); ps += p[j]; }
#pragma unroll
            for (int o = 1; o < 16; o <<= 1)
                ps += __shfl_xor_sync(0xffffffffu, ps, o);
            lrow[i] = lrow[i] * corr + ps;
#pragma unroll
            for (int j = 0; j < 4; j++) O[i][j] *= corr;
            *(float4*)&Ps[(ty * 4 + i) * 68 + tx * 4] =
                make_float4(p[0], p[1], p[2], p[3]);
        }
        __syncthreads();

        // PV with float4 P loads
#pragma unroll 4
        for (int jb = 0; jb < 64; jb += 4) {
            const float4 p0 = *(const float4*)&Ps[(ty * 4 + 0) * 68 + jb];
            const float4 p1 = *(const float4*)&Ps[(ty * 4 + 1) * 68 + jb];
            const float4 p2 = *(const float4*)&Ps[(ty * 4 + 2) * 68 + jb];
            const float4 p3 = *(const float4*)&Ps[(ty * 4 + 3) * 68 + jb];
            const float pr[4][4] = {{p0.x, p0.y, p0.z, p0.w},
                                    {p1.x, p1.y, p1.z, p1.w},
                                    {p2.x, p2.y, p2.z, p2.w},
                                    {p3.x, p3.y, p3.z, p3.w}};
#pragma unroll
            for (int jj = 0; jj < 4; jj++) {
                const float4 vv = *(const float4*)&Vs[(jb + jj) * 64 + tx * 4];
                const float vr[4] = {vv.x, vv.y, vv.z, vv.w};
#pragma unroll
                for (int i = 0; i < 4; i++)
#pragma unroll
                    for (int c = 0; c < 4; c++)
                        O[i][c] = fmaf(pr[i][jj], vr[c], O[i][c]);
            }
        }
    }

    float* wb = g_wv + (size_t)n * 524288 + (size_t)head * 65536;
#pragma unroll
    for (int i = 0; i < 4; i++) {
        const float inv = 1.f / lrow[i];
        const int row = i0 + ty * 4 + i;
        *(float4*)&wb[(size_t)row * 64 + tx * 4] =
            make_float4(O[i][0] * inv, O[i][1] * inv, O[i][2] * inv, O[i][3] * inv);
    }
}

// ---------------------------------------------------------------------------
// Launch
// ---------------------------------------------------------------------------
extern "C" void kernel_launch(void* const* d_in, const int* in_sizes, int n_in,
                              void* d_out, int out_size) {
    const float* x     = (const float*)d_in[0];
    const float* gw    = (const float*)d_in[1];
    const float* gb    = (const float*)d_in[2];
    const float* qkv_w = (const float*)d_in[3];
    const float* qkv_b = (const float*)d_in[4];
    const float* out_w = (const float*)d_in[5];
    const float* out_b = (const float*)d_in[6];
    float* out = (float*)d_out;

    float *xn_p, *qkv_p, *wv_p;
    cudaGetSymbolAddress((void**)&xn_p,  g_xn);
    cudaGetSymbolAddress((void**)&qkv_p, g_qkv);
    cudaGetSymbolAddress((void**)&wv_p,  g_wv);

    cudaFuncSetAttribute(attn_kernel,
                         cudaFuncAttributeMaxDynamicSharedMemorySize, 66560);

    gn_kernel<<<dim3(32, 8), 256>>>(x, gw, gb);
    mma_gemm<<<dim3(8, 12, 8), 256>>>(qkv_w, qkv_b, xn_p, qkv_p, 1536);
    vtrans_kernel<<<dim3(32, 2, 64), dim3(32, 8)>>>();
    attn_kernel<<<dim3(16, 64), 256, 66560>>>();
    mma_gemm<<<dim3(8, 4, 8), 256>>>(out_w, out_b, wv_p, out, 512);
}

// round 13
// speedup vs baseline: 2.7729x; 1.9060x over previous
#include <cuda_runtime.h>
#include <math.h>
#include <stdint.h>

// x: [8, 512, 32, 32] -> [8, 512, 1024]; heads=8, cph=64, groups=32, eps=1e-5

// ---------------------------------------------------------------------------
// Scratch (device globals; no dynamic allocation allowed)
// ---------------------------------------------------------------------------
__device__ float g_xn  [8 * 512 * 1024];       // GroupNorm output            16 MB
__device__ float g_qkv [8 * 1536 * 1024];      // QKV projection              48 MB
__device__ float g_qt  [64 * 1024 * 64];       // Q transposed [bh][i][c]     16 MB
__device__ float g_vt  [64 * 1024 * 64];       // V transposed [bh][j][c]     16 MB
__device__ float g_wv  [8 * 512 * 1024];       // attention out (flat view)   16 MB

__device__ __forceinline__ float to_tf32(float x) {
    float y; asm("cvt.rna.tf32.f32 %0, %1;" : "=f"(y) : "f"(x)); return y;
}
__device__ __forceinline__ void mma_tf32_16x8x8(
    float& d0, float& d1, float& d2, float& d3,
    uint32_t a0, uint32_t a1, uint32_t a2, uint32_t a3,
    uint32_t b0, uint32_t b1) {
    asm volatile(
        "mma.sync.aligned.m16n8k8.row.col.f32.tf32.tf32.f32 "
        "{%0,%1,%2,%3}, {%4,%5,%6,%7}, {%8,%9}, {%0,%1,%2,%3};"
        : "+f"(d0), "+f"(d1), "+f"(d2), "+f"(d3)
        : "r"(a0), "r"(a1), "r"(a2), "r"(a3), "r"(b0), "r"(b1));
}

// ---------------------------------------------------------------------------
// GroupNorm
// ---------------------------------------------------------------------------
__global__ void gn_kernel(const float* __restrict__ x,
                          const float* __restrict__ gw,
                          const float* __restrict__ gb) {
    const int g = blockIdx.x, n = blockIdx.y;
    const float* xp = x + ((size_t)n * 512 + (size_t)g * 16) * 1024;
    float s = 0.f, s2 = 0.f;
    for (int i = threadIdx.x; i < 16384; i += 256) {
        float v = xp[i]; s += v; s2 += v * v;
    }
    __shared__ float rs[8], rs2[8];
#pragma unroll
    for (int o = 16; o; o >>= 1) {
        s  += __shfl_xor_sync(0xffffffffu, s,  o);
        s2 += __shfl_xor_sync(0xffffffffu, s2, o);
    }
    const int wid = threadIdx.x >> 5, lane = threadIdx.x & 31;
    if (lane == 0) { rs[wid] = s; rs2[wid] = s2; }
    __syncthreads();
    if (threadIdx.x < 32) {
        s  = (threadIdx.x < 8) ? rs [threadIdx.x] : 0.f;
        s2 = (threadIdx.x < 8) ? rs2[threadIdx.x] : 0.f;
#pragma unroll
        for (int o = 4; o; o >>= 1) {
            s  += __shfl_xor_sync(0xffffffffu, s,  o);
            s2 += __shfl_xor_sync(0xffffffffu, s2, o);
        }
        if (threadIdx.x == 0) { rs[0] = s; rs2[0] = s2; }
    }
    __syncthreads();
    const float mean = rs[0] * (1.f / 16384.f);
    const float var  = rs2[0] * (1.f / 16384.f) - mean * mean;
    const float rstd = rsqrtf(var + 1e-5f);
    float* op = g_xn + ((size_t)n * 512 + (size_t)g * 16) * 1024;
    for (int i = threadIdx.x; i < 16384; i += 256) {
        const int ch = g * 16 + (i >> 10);
        op[i] = (xp[i] - mean) * rstd * gw[ch] + gb[ch];
    }
}

// ---------------------------------------------------------------------------
// tf32 mma.sync GEMM:  Y[nb][m][n] = sum_k W[m][k] * B[nb][k][n] + bias[m]
// ---------------------------------------------------------------------------
__global__ __launch_bounds__(256)
void mma_gemm(const float* __restrict__ W, const float* __restrict__ bias,
              const float* __restrict__ B, float* __restrict__ Y, int M) {
    __shared__ float As[128 * 36];   // [m][k]
    __shared__ float Bs[32 * 136];   // [k][n]

    const int tid = threadIdx.x, w = tid >> 5, lane = tid & 31;
    const int n0 = blockIdx.x * 128, m0 = blockIdx.y * 128, nb = blockIdx.z;
    const float* Bb = B + (size_t)nb * 512 * 1024;
    float* Yb = Y + (size_t)nb * M * 1024;

    const int wm = (w >> 2) * 64;
    const int wn = (w & 3) * 32;
    const int gid = lane >> 2;
    const int tig = lane & 3;

    float acc[4][4][4] = {};

    float4 pa[4], pb[4];
#pragma unroll
    for (int v = 0; v < 4; v++) {
        const int fa = tid + 256 * v;
        pa[v] = *(const float4*)&W [(size_t)(m0 + (fa >> 3)) * 512 + (fa & 7) * 4];
        const int fb = tid + 256 * v;
        pb[v] = *(const float4*)&Bb[(size_t)(fb >> 5) * 1024 + n0 + (fb & 31) * 4];
    }

    for (int kc = 0; kc < 16; kc++) {
        __syncthreads();
#pragma unroll
        for (int v = 0; v < 4; v++) {
            const int fa = tid + 256 * v;
            float4 a = pa[v];
            a.x = to_tf32(a.x); a.y = to_tf32(a.y); a.z = to_tf32(a.z); a.w = to_tf32(a.w);
            *(float4*)&As[(fa >> 3) * 36 + (fa & 7) * 4] = a;
            const int fb = tid + 256 * v;
            float4 b = pb[v];
            b.x = to_tf32(b.x); b.y = to_tf32(b.y); b.z = to_tf32(b.z); b.w = to_tf32(b.w);
            *(float4*)&Bs[(fb >> 5) * 136 + (fb & 31) * 4] = b;
        }
        __syncthreads();

        if (kc < 15) {
            const int k0 = (kc + 1) * 32;
#pragma unroll
            for (int v = 0; v < 4; v++) {
                const int fa = tid + 256 * v;
                pa[v] = *(const float4*)&W [(size_t)(m0 + (fa >> 3)) * 512 + k0 + (fa & 7) * 4];
                const int fb = tid + 256 * v;
                pb[v] = *(const float4*)&Bb[(size_t)(k0 + (fb >> 5)) * 1024 + n0 + (fb & 31) * 4];
            }
        }

#pragma unroll
        for (int ks = 0; ks < 4; ks++) {
            const int kk = ks * 8;
            uint32_t af[4][4];
#pragma unroll
            for (int mt = 0; mt < 4; mt++) {
                const int r = (wm + mt * 16 + gid) * 36 + kk + tig;
                af[mt][0] = __float_as_uint(As[r]);
                af[mt][1] = __float_as_uint(As[r + 8 * 36]);
                af[mt][2] = __float_as_uint(As[r + 4]);
                af[mt][3] = __float_as_uint(As[r + 8 * 36 + 4]);
            }
            uint32_t bf[4][2];
#pragma unroll
            for (int nt = 0; nt < 4; nt++) {
                const int c = (kk + tig) * 136 + wn + nt * 8 + gid;
                bf[nt][0] = __float_as_uint(Bs[c]);
                bf[nt][1] = __float_as_uint(Bs[c + 4 * 136]);
            }
#pragma unroll
            for (int mt = 0; mt < 4; mt++)
#pragma unroll
                for (int nt = 0; nt < 4; nt++)
                    mma_tf32_16x8x8(acc[mt][nt][0], acc[mt][nt][1],
                                    acc[mt][nt][2], acc[mt][nt][3],
                                    af[mt][0], af[mt][1], af[mt][2], af[mt][3],
                                    bf[nt][0], bf[nt][1]);
        }
    }

#pragma unroll
    for (int mt = 0; mt < 4; mt++) {
        const int r0 = m0 + wm + mt * 16 + gid;
        const float bv0 = bias[r0], bv1 = bias[r0 + 8];
#pragma unroll
        for (int nt = 0; nt < 4; nt++) {
            const int col = n0 + wn + nt * 8 + tig * 2;
            *(float2*)&Yb[(size_t)r0 * 1024 + col] =
                make_float2(acc[mt][nt][0] + bv0, acc[mt][nt][1] + bv0);
            *(float2*)&Yb[(size_t)(r0 + 8) * 1024 + col] =
                make_float2(acc[mt][nt][2] + bv1, acc[mt][nt][3] + bv1);
        }
    }
}

// ---------------------------------------------------------------------------
// Q/V transpose: qkv section [c][i] -> [bh][i][c]
// grid (32 i-tiles, 2 c-tiles, 128 = bh*2+qv), block (32, 8)
// ---------------------------------------------------------------------------
__global__ void qvtrans_kernel() {
    __shared__ float t[32][33];
    const int qv = blockIdx.z & 1;
    const int bh = blockIdx.z >> 1;
    const int n = bh >> 3, head = bh & 7;
    const float* src = g_qkv +
        ((size_t)n * 1536 + (qv ? 1024 : 0) + (size_t)head * 64) * 1024;
    float* dst = (qv ? g_vt : g_qt) + (size_t)bh * 65536;
    const int j0 = blockIdx.x * 32, c0 = blockIdx.y * 32;
    for (int r = threadIdx.y; r < 32; r += 8)
        t[r][threadIdx.x] = src[(size_t)(c0 + r) * 1024 + j0 + threadIdx.x];
    __syncthreads();
    float* o = dst + (size_t)j0 * 64 + c0;
    for (int r = threadIdx.y; r < 32; r += 8)
        o[(size_t)r * 64 + threadIdx.x] = t[threadIdx.x][r];
}

// ---------------------------------------------------------------------------
// Tensor-core flash attention: seq 1024, d 64.
// grid(16 i-tiles, 64 bh), block 128 (4 warps); warp w owns i-rows w*16..w*16+15.
// QK^T: A = Qt[i][c] (frags cached in regs), B = K native [c][j].
// PV:   A = P[i][j] (smem staged, warp-private rows), B = Vt[j][c].
// ---------------------------------------------------------------------------
#define KV_STRIDE 72
#define P_STRIDE  68
#define ATTN_SMEM ((64 * KV_STRIDE * 2 + 64 * P_STRIDE) * 4)

__global__ __launch_bounds__(128)
void attn_mma_kernel() {
    extern __shared__ float sm[];
    float* Ks = sm;                       // [c][j] stride 72
    float* Vs = sm + 64 * KV_STRIDE;      // [j][c] stride 72
    float* Ps = sm + 128 * KV_STRIDE;     // [i][j] stride 68 (also Q staging)

    const int tid = threadIdx.x;
    const int w = tid >> 5, lane = tid & 31;
    const int gid = lane >> 2, tig = lane & 3;
    const int wm = w * 16;
    const int bh = blockIdx.y, n = bh >> 3, head = bh & 7;
    const int i0 = blockIdx.x * 64;

    const float* qt = g_qt + (size_t)bh * 65536;                       // [i][c]
    const float* kg = g_qkv + ((size_t)n * 1536 + 512 + (size_t)head * 64) * 1024; // [c][j]
    const float* vt = g_vt + (size_t)bh * 65536;                       // [j][c]

    // Stage Q tile (scaled, tf32) into Ps, then extract A-fragments to regs.
#pragma unroll
    for (int v = 0; v < 8; v++) {
        const int f = tid + 128 * v;          // 0..1023
        const int r = f >> 4, c4 = (f & 15) * 4;
        float4 q = *(const float4*)&qt[(size_t)(i0 + r) * 64 + c4];
        q.x = to_tf32(q.x * 0.125f); q.y = to_tf32(q.y * 0.125f);
        q.z = to_tf32(q.z * 0.125f); q.w = to_tf32(q.w * 0.125f);
        *(float4*)&Ps[r * P_STRIDE + c4] = q;
    }
    __syncthreads();
    uint32_t qf[8][4];
#pragma unroll
    for (int ks = 0; ks < 8; ks++) {
        const int base = ks * 8 + tig;
        qf[ks][0] = __float_as_uint(Ps[(wm + gid)     * P_STRIDE + base]);
        qf[ks][1] = __float_as_uint(Ps[(wm + gid + 8) * P_STRIDE + base]);
        qf[ks][2] = __float_as_uint(Ps[(wm + gid)     * P_STRIDE + base + 4]);
        qf[ks][3] = __float_as_uint(Ps[(wm + gid + 8) * P_STRIDE + base + 4]);
    }

    float oacc[8][4] = {};
    float m0 = -1e30f, m1 = -1e30f, l0 = 0.f, l1 = 0.f;

    for (int jt = 0; jt < 16; jt++) {
        const int j0 = jt * 64;
        __syncthreads();   // protect Ks/Vs/Ps overwrite vs prior reads
#pragma unroll
        for (int v = 0; v < 8; v++) {
            const int f = tid + 128 * v;
            const int r = f >> 4, c4 = (f & 15) * 4;
            float4 kk = *(const float4*)&kg[(size_t)r * 1024 + j0 + c4];
            kk.x = to_tf32(kk.x); kk.y = to_tf32(kk.y);
            kk.z = to_tf32(kk.z); kk.w = to_tf32(kk.w);
            *(float4*)&Ks[r * KV_STRIDE + c4] = kk;
            float4 vv = *(const float4*)&vt[(size_t)(j0 + r) * 64 + c4];
            vv.x = to_tf32(vv.x); vv.y = to_tf32(vv.y);
            vv.z = to_tf32(vv.z); vv.w = to_tf32(vv.w);
            *(float4*)&Vs[r * KV_STRIDE + c4] = vv;
        }
        __syncthreads();

        // S = Q K^T  (per warp: m16 x n64)
        float sacc[8][4] = {};
#pragma unroll
        for (int ks = 0; ks < 8; ks++) {
            const int r0 = (ks * 8 + tig) * KV_STRIDE;
            const int r1 = (ks * 8 + tig + 4) * KV_STRIDE;
#pragma unroll
            for (int nt = 0; nt < 8; nt++) {
                const uint32_t b0 = __float_as_uint(Ks[r0 + nt * 8 + gid]);
                const uint32_t b1 = __float_as_uint(Ks[r1 + nt * 8 + gid]);
                mma_tf32_16x8x8(sacc[nt][0], sacc[nt][1], sacc[nt][2], sacc[nt][3],
                                qf[ks][0], qf[ks][1], qf[ks][2], qf[ks][3], b0, b1);
            }
        }

        // Online softmax (rows gid / gid+8, spread across the quad)
        float tm0 = -1e30f, tm1 = -1e30f;
#pragma unroll
        for (int nt = 0; nt < 8; nt++) {
            tm0 = fmaxf(tm0, fmaxf(sacc[nt][0], sacc[nt][1]));
            tm1 = fmaxf(tm1, fmaxf(sacc[nt][2], sacc[nt][3]));
        }
        tm0 = fmaxf(tm0, __shfl_xor_sync(0xffffffffu, tm0, 1));
        tm0 = fmaxf(tm0, __shfl_xor_sync(0xffffffffu, tm0, 2));
        tm1 = fmaxf(tm1, __shfl_xor_sync(0xffffffffu, tm1, 1));
        tm1 = fmaxf(tm1, __shfl_xor_sync(0xffffffffu, tm1, 2));
        const float mn0 = fmaxf(m0, tm0), mn1 = fmaxf(m1, tm1);
        const float c0 = __expf(m0 - mn0), c1 = __expf(m1 - mn1);
        m0 = mn0; m1 = mn1;
        float s0 = 0.f, s1 = 0.f;
#pragma unroll
        for (int nt = 0; nt < 8; nt++) {
            sacc[nt][0] = __expf(sacc[nt][0] - m0); s0 += sacc[nt][0];
            sacc[nt][1] = __expf(sacc[nt][1] - m0); s0 += sacc[nt][1];
            sacc[nt][2] = __expf(sacc[nt][2] - m1); s1 += sacc[nt][2];
            sacc[nt][3] = __expf(sacc[nt][3] - m1); s1 += sacc[nt][3];
        }
        s0 += __shfl_xor_sync(0xffffffffu, s0, 1);
        s0 += __shfl_xor_sync(0xffffffffu, s0, 2);
        s1 += __shfl_xor_sync(0xffffffffu, s1, 1);
        s1 += __shfl_xor_sync(0xffffffffu, s1, 2);
        l0 = l0 * c0 + s0;
        l1 = l1 * c1 + s1;
#pragma unroll
        for (int nt = 0; nt < 8; nt++) {
            oacc[nt][0] *= c0; oacc[nt][1] *= c0;
            oacc[nt][2] *= c1; oacc[nt][3] *= c1;
        }

        // Store P (tf32) to warp-private rows of Ps
        float* pr0 = &Ps[(wm + gid)     * P_STRIDE];
        float* pr1 = &Ps[(wm + gid + 8) * P_STRIDE];
#pragma unroll
        for (int nt = 0; nt < 8; nt++) {
            const int col = nt * 8 + tig * 2;
            *(float2*)&pr0[col] = make_float2(to_tf32(sacc[nt][0]), to_tf32(sacc[nt][1]));
            *(float2*)&pr1[col] = make_float2(to_tf32(sacc[nt][2]), to_tf32(sacc[nt][3]));
        }
        __syncwarp();

        // O += P V  (A = P[i][j], B = Vt[j][c])
#pragma unroll
        for (int ks = 0; ks < 8; ks++) {
            const int base = ks * 8 + tig;
            const uint32_t a0 = __float_as_uint(pr0[base]);
            const uint32_t a1 = __float_as_uint(pr1[base]);
            const uint32_t a2 = __float_as_uint(pr0[base + 4]);
            const uint32_t a3 = __float_as_uint(pr1[base + 4]);
            const int r0 = (ks * 8 + tig) * KV_STRIDE;
            const int r1 = (ks * 8 + tig + 4) * KV_STRIDE;
#pragma unroll
            for (int nt = 0; nt < 8; nt++) {
                const uint32_t b0 = __float_as_uint(Vs[r0 + nt * 8 + gid]);
                const uint32_t b1 = __float_as_uint(Vs[r1 + nt * 8 + gid]);
                mma_tf32_16x8x8(oacc[nt][0], oacc[nt][1], oacc[nt][2], oacc[nt][3],
                                a0, a1, a2, a3, b0, b1);
            }
        }
    }

    // Epilogue: normalize, store to torch-faithful flat layout
    const float inv0 = 1.f / l0, inv1 = 1.f / l1;
    float* wb = g_wv + (size_t)n * 524288 + (size_t)head * 65536;
    const int row0 = i0 + wm + gid, row1 = row0 + 8;
#pragma unroll
    for (int nt = 0; nt < 8; nt++) {
        const int col = nt * 8 + tig * 2;
        *(float2*)&wb[(size_t)row0 * 64 + col] =
            make_float2(oacc[nt][0] * inv0, oacc[nt][1] * inv0);
        *(float2*)&wb[(size_t)row1 * 64 + col] =
            make_float2(oacc[nt][2] * inv1, oacc[nt][3] * inv1);
    }
}

// ---------------------------------------------------------------------------
// Launch
// ---------------------------------------------------------------------------
extern "C" void kernel_launch(void* const* d_in, const int* in_sizes, int n_in,
                              void* d_out, int out_size) {
    const float* x     = (const float*)d_in[0];
    const float* gw    = (const float*)d_in[1];
    const float* gb    = (const float*)d_in[2];
    const float* qkv_w = (const float*)d_in[3];
    const float* qkv_b = (const float*)d_in[4];
    const float* out_w = (const float*)d_in[5];
    const float* out_b = (const float*)d_in[6];
    float* out = (float*)d_out;

    float *xn_p, *qkv_p, *wv_p;
    cudaGetSymbolAddress((void**)&xn_p,  g_xn);
    cudaGetSymbolAddress((void**)&qkv_p, g_qkv);
    cudaGetSymbolAddress((void**)&wv_p,  g_wv);

    cudaFuncSetAttribute(attn_mma_kernel,
                         cudaFuncAttributeMaxDynamicSharedMemorySize, ATTN_SMEM);

    gn_kernel<<<dim3(32, 8), 256>>>(x, gw, gb);
    mma_gemm<<<dim3(8, 12, 8), 256>>>(qkv_w, qkv_b, xn_p, qkv_p, 1536);
    qvtrans_kernel<<<dim3(32, 2, 128), dim3(32, 8)>>>();
    attn_mma_kernel<<<dim3(16, 64), 128, ATTN_SMEM>>>();
    mma_gemm<<<dim3(8, 4, 8), 256>>>(out_w, out_b, wv_p, out, 512);
}

// round 14
// speedup vs baseline: 2.7776x; 1.0017x over previous
#include <cuda_runtime.h>
#include <math.h>
#include <stdint.h>

// x: [8, 512, 32, 32] -> [8, 512, 1024]; heads=8, cph=64, groups=32, eps=1e-5

// ---------------------------------------------------------------------------
// Scratch (device globals; no dynamic allocation allowed)
// ---------------------------------------------------------------------------
__device__ float g_xn  [8 * 512 * 1024];       // GroupNorm output            16 MB
__device__ float g_qkv [8 * 1536 * 1024];      // QKV projection              48 MB
__device__ float g_qt  [64 * 1024 * 64];       // Q transposed [bh][i][c]     16 MB
__device__ float g_vt  [64 * 1024 * 64];       // V transposed [bh][j][c]     16 MB
__device__ float g_wv  [8 * 512 * 1024];       // attention out (flat view)   16 MB

__device__ __forceinline__ float to_tf32(float x) {
    float y; asm("cvt.rna.tf32.f32 %0, %1;" : "=f"(y) : "f"(x)); return y;
}
__device__ __forceinline__ void mma_tf32_16x8x8(
    float& d0, float& d1, float& d2, float& d3,
    uint32_t a0, uint32_t a1, uint32_t a2, uint32_t a3,
    uint32_t b0, uint32_t b1) {
    asm volatile(
        "mma.sync.aligned.m16n8k8.row.col.f32.tf32.tf32.f32 "
        "{%0,%1,%2,%3}, {%4,%5,%6,%7}, {%8,%9}, {%0,%1,%2,%3};"
        : "+f"(d0), "+f"(d1), "+f"(d2), "+f"(d3)
        : "r"(a0), "r"(a1), "r"(a2), "r"(a3), "r"(b0), "r"(b1));
}

// ---------------------------------------------------------------------------
// GroupNorm
// ---------------------------------------------------------------------------
__global__ void gn_kernel(const float* __restrict__ x,
                          const float* __restrict__ gw,
                          const float* __restrict__ gb) {
    const int g = blockIdx.x, n = blockIdx.y;
    const float* xp = x + ((size_t)n * 512 + (size_t)g * 16) * 1024;
    float s = 0.f, s2 = 0.f;
    for (int i = threadIdx.x; i < 16384; i += 256) {
        float v = xp[i]; s += v; s2 += v * v;
    }
    __shared__ float rs[8], rs2[8];
#pragma unroll
    for (int o = 16; o; o >>= 1) {
        s  += __shfl_xor_sync(0xffffffffu, s,  o);
        s2 += __shfl_xor_sync(0xffffffffu, s2, o);
    }
    const int wid = threadIdx.x >> 5, lane = threadIdx.x & 31;
    if (lane == 0) { rs[wid] = s; rs2[wid] = s2; }
    __syncthreads();
    if (threadIdx.x < 32) {
        s  = (threadIdx.x < 8) ? rs [threadIdx.x] : 0.f;
        s2 = (threadIdx.x < 8) ? rs2[threadIdx.x] : 0.f;
#pragma unroll
        for (int o = 4; o; o >>= 1) {
            s  += __shfl_xor_sync(0xffffffffu, s,  o);
            s2 += __shfl_xor_sync(0xffffffffu, s2, o);
        }
        if (threadIdx.x == 0) { rs[0] = s; rs2[0] = s2; }
    }
    __syncthreads();
    const float mean = rs[0] * (1.f / 16384.f);
    const float var  = rs2[0] * (1.f / 16384.f) - mean * mean;
    const float rstd = rsqrtf(var + 1e-5f);
    float* op = g_xn + ((size_t)n * 512 + (size_t)g * 16) * 1024;
    for (int i = threadIdx.x; i < 16384; i += 256) {
        const int ch = g * 16 + (i >> 10);
        op[i] = (xp[i] - mean) * rstd * gw[ch] + gb[ch];
    }
}

// ---------------------------------------------------------------------------
// tf32 mma.sync GEMM:  Y[nb][m][n] = sum_k W[m][k] * B[nb][k][n] + bias[m]
// ---------------------------------------------------------------------------
__global__ __launch_bounds__(256)
void mma_gemm(const float* __restrict__ W, const float* __restrict__ bias,
              const float* __restrict__ B, float* __restrict__ Y, int M) {
    __shared__ float As[128 * 36];   // [m][k]
    __shared__ float Bs[32 * 136];   // [k][n]

    const int tid = threadIdx.x, w = tid >> 5, lane = tid & 31;
    const int n0 = blockIdx.x * 128, m0 = blockIdx.y * 128, nb = blockIdx.z;
    const float* Bb = B + (size_t)nb * 512 * 1024;
    float* Yb = Y + (size_t)nb * M * 1024;

    const int wm = (w >> 2) * 64;
    const int wn = (w & 3) * 32;
    const int gid = lane >> 2;
    const int tig = lane & 3;

    float acc[4][4][4] = {};

    float4 pa[4], pb[4];
#pragma unroll
    for (int v = 0; v < 4; v++) {
        const int fa = tid + 256 * v;
        pa[v] = *(const float4*)&W [(size_t)(m0 + (fa >> 3)) * 512 + (fa & 7) * 4];
        const int fb = tid + 256 * v;
        pb[v] = *(const float4*)&Bb[(size_t)(fb >> 5) * 1024 + n0 + (fb & 31) * 4];
    }

    for (int kc = 0; kc < 16; kc++) {
        __syncthreads();
#pragma unroll
        for (int v = 0; v < 4; v++) {
            const int fa = tid + 256 * v;
            float4 a = pa[v];
            a.x = to_tf32(a.x); a.y = to_tf32(a.y); a.z = to_tf32(a.z); a.w = to_tf32(a.w);
            *(float4*)&As[(fa >> 3) * 36 + (fa & 7) * 4] = a;
            const int fb = tid + 256 * v;
            float4 b = pb[v];
            b.x = to_tf32(b.x); b.y = to_tf32(b.y); b.z = to_tf32(b.z); b.w = to_tf32(b.w);
            *(float4*)&Bs[(fb >> 5) * 136 + (fb & 31) * 4] = b;
        }
        __syncthreads();

        if (kc < 15) {
            const int k0 = (kc + 1) * 32;
#pragma unroll
            for (int v = 0; v < 4; v++) {
                const int fa = tid + 256 * v;
                pa[v] = *(const float4*)&W [(size_t)(m0 + (fa >> 3)) * 512 + k0 + (fa & 7) * 4];
                const int fb = tid + 256 * v;
                pb[v] = *(const float4*)&Bb[(size_t)(k0 + (fb >> 5)) * 1024 + n0 + (fb & 31) * 4];
            }
        }

#pragma unroll
        for (int ks = 0; ks < 4; ks++) {
            const int kk = ks * 8;
            uint32_t af[4][4];
#pragma unroll
            for (int mt = 0; mt < 4; mt++) {
                const int r = (wm + mt * 16 + gid) * 36 + kk + tig;
                af[mt][0] = __float_as_uint(As[r]);
                af[mt][1] = __float_as_uint(As[r + 8 * 36]);
                af[mt][2] = __float_as_uint(As[r + 4]);
                af[mt][3] = __float_as_uint(As[r + 8 * 36 + 4]);
            }
            uint32_t bf[4][2];
#pragma unroll
            for (int nt = 0; nt < 4; nt++) {
                const int c = (kk + tig) * 136 + wn + nt * 8 + gid;
                bf[nt][0] = __float_as_uint(Bs[c]);
                bf[nt][1] = __float_as_uint(Bs[c + 4 * 136]);
            }
#pragma unroll
            for (int mt = 0; mt < 4; mt++)
#pragma unroll
                for (int nt = 0; nt < 4; nt++)
                    mma_tf32_16x8x8(acc[mt][nt][0], acc[mt][nt][1],
                                    acc[mt][nt][2], acc[mt][nt][3],
                                    af[mt][0], af[mt][1], af[mt][2], af[mt][3],
                                    bf[nt][0], bf[nt][1]);
        }
    }

#pragma unroll
    for (int mt = 0; mt < 4; mt++) {
        const int r0 = m0 + wm + mt * 16 + gid;
        const float bv0 = bias[r0], bv1 = bias[r0 + 8];
#pragma unroll
        for (int nt = 0; nt < 4; nt++) {
            const int col = n0 + wn + nt * 8 + tig * 2;
            *(float2*)&Yb[(size_t)r0 * 1024 + col] =
                make_float2(acc[mt][nt][0] + bv0, acc[mt][nt][1] + bv0);
            *(float2*)&Yb[(size_t)(r0 + 8) * 1024 + col] =
                make_float2(acc[mt][nt][2] + bv1, acc[mt][nt][3] + bv1);
        }
    }
}

// ---------------------------------------------------------------------------
// Q/V transpose: qkv section [c][i] -> [bh][i][c]
// grid (32 i-tiles, 2 c-tiles, 128 = bh*2+qv), block (32, 8)
// ---------------------------------------------------------------------------
__global__ void qvtrans_kernel() {
    __shared__ float t[32][33];
    const int qv = blockIdx.z & 1;
    const int bh = blockIdx.z >> 1;
    const int n = bh >> 3, head = bh & 7;
    const float* src = g_qkv +
        ((size_t)n * 1536 + (qv ? 1024 : 0) + (size_t)head * 64) * 1024;
    float* dst = (qv ? g_vt : g_qt) + (size_t)bh * 65536;
    const int j0 = blockIdx.x * 32, c0 = blockIdx.y * 32;
    for (int r = threadIdx.y; r < 32; r += 8)
        t[r][threadIdx.x] = src[(size_t)(c0 + r) * 1024 + j0 + threadIdx.x];
    __syncthreads();
    float* o = dst + (size_t)j0 * 64 + c0;
    for (int r = threadIdx.y; r < 32; r += 8)
        o[(size_t)r * 64 + threadIdx.x] = t[threadIdx.x][r];
}

// ---------------------------------------------------------------------------
// Tensor-core flash attention: seq 1024, d 64.
// grid(16 i-tiles, 64 bh), block 128 (4 warps); warp w owns i-rows w*16..w*16+15.
// QK^T: A = Qt[i][c] (frags cached in regs), B = K native [c][j].
// PV:   A = P[i][j] (smem staged, warp-private rows), B = Vt[j][c].
// ---------------------------------------------------------------------------
#define KV_STRIDE 72
#define P_STRIDE  68
#define ATTN_SMEM ((64 * KV_STRIDE * 2 + 64 * P_STRIDE) * 4)

__global__ __launch_bounds__(128)
void attn_mma_kernel() {
    extern __shared__ float sm[];
    float* Ks = sm;                       // [c][j] stride 72
    float* Vs = sm + 64 * KV_STRIDE;      // [j][c] stride 72
    float* Ps = sm + 128 * KV_STRIDE;     // [i][j] stride 68 (also Q staging)

    const int tid = threadIdx.x;
    const int w = tid >> 5, lane = tid & 31;
    const int gid = lane >> 2, tig = lane & 3;
    const int wm = w * 16;
    const int bh = blockIdx.y, n = bh >> 3, head = bh & 7;
    const int i0 = blockIdx.x * 64;

    const float* qt = g_qt + (size_t)bh * 65536;                       // [i][c]
    const float* kg = g_qkv + ((size_t)n * 1536 + 512 + (size_t)head * 64) * 1024; // [c][j]
    const float* vt = g_vt + (size_t)bh * 65536;                       // [j][c]

    // Stage Q tile (scaled, tf32) into Ps, then extract A-fragments to regs.
#pragma unroll
    for (int v = 0; v < 8; v++) {
        const int f = tid + 128 * v;          // 0..1023
        const int r = f >> 4, c4 = (f & 15) * 4;
        float4 q = *(const float4*)&qt[(size_t)(i0 + r) * 64 + c4];
        q.x = to_tf32(q.x * 0.125f); q.y = to_tf32(q.y * 0.125f);
        q.z = to_tf32(q.z * 0.125f); q.w = to_tf32(q.w * 0.125f);
        *(float4*)&Ps[r * P_STRIDE + c4] = q;
    }
    __syncthreads();
    uint32_t qf[8][4];
#pragma unroll
    for (int ks = 0; ks < 8; ks++) {
        const int base = ks * 8 + tig;
        qf[ks][0] = __float_as_uint(Ps[(wm + gid)     * P_STRIDE + base]);
        qf[ks][1] = __float_as_uint(Ps[(wm + gid + 8) * P_STRIDE + base]);
        qf[ks][2] = __float_as_uint(Ps[(wm + gid)     * P_STRIDE + base + 4]);
        qf[ks][3] = __float_as_uint(Ps[(wm + gid + 8) * P_STRIDE + base + 4]);
    }

    float oacc[8][4] = {};
    float m0 = -1e30f, m1 = -1e30f, l0 = 0.f, l1 = 0.f;

    for (int jt = 0; jt < 16; jt++) {
        const int j0 = jt * 64;
        __syncthreads();   // protect Ks/Vs/Ps overwrite vs prior reads
#pragma unroll
        for (int v = 0; v < 8; v++) {
            const int f = tid + 128 * v;
            const int r = f >> 4, c4 = (f & 15) * 4;
            float4 kk = *(const float4*)&kg[(size_t)r * 1024 + j0 + c4];
            kk.x = to_tf32(kk.x); kk.y = to_tf32(kk.y);
            kk.z = to_tf32(kk.z); kk.w = to_tf32(kk.w);
            *(float4*)&Ks[r * KV_STRIDE + c4] = kk;
            float4 vv = *(const float4*)&vt[(size_t)(j0 + r) * 64 + c4];
            vv.x = to_tf32(vv.x); vv.y = to_tf32(vv.y);
            vv.z = to_tf32(vv.z); vv.w = to_tf32(vv.w);
            *(float4*)&Vs[r * KV_STRIDE + c4] = vv;
        }
        __syncthreads();

        // S = Q K^T  (per warp: m16 x n64)
        float sacc[8][4] = {};
#pragma unroll
        for (int ks = 0; ks < 8; ks++) {
            const int r0 = (ks * 8 + tig) * KV_STRIDE;
            const int r1 = (ks * 8 + tig + 4) * KV_STRIDE;
#pragma unroll
            for (int nt = 0; nt < 8; nt++) {
                const uint32_t b0 = __float_as_uint(Ks[r0 + nt * 8 + gid]);
                const uint32_t b1 = __float_as_uint(Ks[r1 + nt * 8 + gid]);
                mma_tf32_16x8x8(sacc[nt][0], sacc[nt][1], sacc[nt][2], sacc[nt][3],
                                qf[ks][0], qf[ks][1], qf[ks][2], qf[ks][3], b0, b1);
            }
        }

        // Online softmax (rows gid / gid+8, spread across the quad)
        float tm0 = -1e30f, tm1 = -1e30f;
#pragma unroll
        for (int nt = 0; nt < 8; nt++) {
            tm0 = fmaxf(tm0, fmaxf(sacc[nt][0], sacc[nt][1]));
            tm1 = fmaxf(tm1, fmaxf(sacc[nt][2], sacc[nt][3]));
        }
        tm0 = fmaxf(tm0, __shfl_xor_sync(0xffffffffu, tm0, 1));
        tm0 = fmaxf(tm0, __shfl_xor_sync(0xffffffffu, tm0, 2));
        tm1 = fmaxf(tm1, __shfl_xor_sync(0xffffffffu, tm1, 1));
        tm1 = fmaxf(tm1, __shfl_xor_sync(0xffffffffu, tm1, 2));
        const float mn0 = fmaxf(m0, tm0), mn1 = fmaxf(m1, tm1);
        const float c0 = __expf(m0 - mn0), c1 = __expf(m1 - mn1);
        m0 = mn0; m1 = mn1;
        float s0 = 0.f, s1 = 0.f;
#pragma unroll
        for (int nt = 0; nt < 8; nt++) {
            sacc[nt][0] = __expf(sacc[nt][0] - m0); s0 += sacc[nt][0];
            sacc[nt][1] = __expf(sacc[nt][1] - m0); s0 += sacc[nt][1];
            sacc[nt][2] = __expf(sacc[nt][2] - m1); s1 += sacc[nt][2];
            sacc[nt][3] = __expf(sacc[nt][3] - m1); s1 += sacc[nt][3];
        }
        s0 += __shfl_xor_sync(0xffffffffu, s0, 1);
        s0 += __shfl_xor_sync(0xffffffffu, s0, 2);
        s1 += __shfl_xor_sync(0xffffffffu, s1, 1);
        s1 += __shfl_xor_sync(0xffffffffu, s1, 2);
        l0 = l0 * c0 + s0;
        l1 = l1 * c1 + s1;
#pragma unroll
        for (int nt = 0; nt < 8; nt++) {
            oacc[nt][0] *= c0; oacc[nt][1] *= c0;
            oacc[nt][2] *= c1; oacc[nt][3] *= c1;
        }

        // Store P (tf32) to warp-private rows of Ps
        float* pr0 = &Ps[(wm + gid)     * P_STRIDE];
        float* pr1 = &Ps[(wm + gid + 8) * P_STRIDE];
#pragma unroll
        for (int nt = 0; nt < 8; nt++) {
            const int col = nt * 8 + tig * 2;
            *(float2*)&pr0[col] = make_float2(to_tf32(sacc[nt][0]), to_tf32(sacc[nt][1]));
            *(float2*)&pr1[col] = make_float2(to_tf32(sacc[nt][2]), to_tf32(sacc[nt][3]));
        }
        __syncwarp();

        // O += P V  (A = P[i][j], B = Vt[j][c])
#pragma unroll
        for (int ks = 0; ks < 8; ks++) {
            const int base = ks * 8 + tig;
            const uint32_t a0 = __float_as_uint(pr0[base]);
            const uint32_t a1 = __float_as_uint(pr1[base]);
            const uint32_t a2 = __float_as_uint(pr0[base + 4]);
            const uint32_t a3 = __float_as_uint(pr1[base + 4]);
            const int r0 = (ks * 8 + tig) * KV_STRIDE;
            const int r1 = (ks * 8 + tig + 4) * KV_STRIDE;
#pragma unroll
            for (int nt = 0; nt < 8; nt++) {
                const uint32_t b0 = __float_as_uint(Vs[r0 + nt * 8 + gid]);
                const uint32_t b1 = __float_as_uint(Vs[r1 + nt * 8 + gid]);
                mma_tf32_16x8x8(oacc[nt][0], oacc[nt][1], oacc[nt][2], oacc[nt][3],
                                a0, a1, a2, a3, b0, b1);
            }
        }
    }

    // Epilogue: normalize, store to torch-faithful flat layout
    const float inv0 = 1.f / l0, inv1 = 1.f / l1;
    float* wb = g_wv + (size_t)n * 524288 + (size_t)head * 65536;
    const int row0 = i0 + wm + gid, row1 = row0 + 8;
#pragma unroll
    for (int nt = 0; nt < 8; nt++) {
        const int col = nt * 8 + tig * 2;
        *(float2*)&wb[(size_t)row0 * 64 + col] =
            make_float2(oacc[nt][0] * inv0, oacc[nt][1] * inv0);
        *(float2*)&wb[(size_t)row1 * 64 + col] =
            make_float2(oacc[nt][2] * inv1, oacc[nt][3] * inv1);
    }
}

// ---------------------------------------------------------------------------
// Launch
// ---------------------------------------------------------------------------
extern "C" void kernel_launch(void* const* d_in, const int* in_sizes, int n_in,
                              void* d_out, int out_size) {
    const float* x     = (const float*)d_in[0];
    const float* gw    = (const float*)d_in[1];
    const float* gb    = (const float*)d_in[2];
    const float* qkv_w = (const float*)d_in[3];
    const float* qkv_b = (const float*)d_in[4];
    const float* out_w = (const float*)d_in[5];
    const float* out_b = (const float*)d_in[6];
    float* out = (float*)d_out;

    float *xn_p, *qkv_p, *wv_p;
    cudaGetSymbolAddress((void**)&xn_p,  g_xn);
    cudaGetSymbolAddress((void**)&qkv_p, g_qkv);
    cudaGetSymbolAddress((void**)&wv_p,  g_wv);

    cudaFuncSetAttribute(attn_mma_kernel,
                         cudaFuncAttributeMaxDynamicSharedMemorySize, ATTN_SMEM);

    gn_kernel<<<dim3(32, 8), 256>>>(x, gw, gb);
    mma_gemm<<<dim3(8, 12, 8), 256>>>(qkv_w, qkv_b, xn_p, qkv_p, 1536);
    qvtrans_kernel<<<dim3(32, 2, 128), dim3(32, 8)>>>();
    attn_mma_kernel<<<dim3(16, 64), 128, ATTN_SMEM>>>();
    mma_gemm<<<dim3(8, 4, 8), 256>>>(out_w, out_b, wv_p, out, 512);
}

// round 16
// speedup vs baseline: 2.7829x; 1.0019x over previous
#include <cuda_runtime.h>
#include <math.h>
#include <stdint.h>

// x: [8, 512, 32, 32] -> [8, 512, 1024]; heads=8, cph=64, groups=32, eps=1e-5

// ---------------------------------------------------------------------------
// Scratch (device globals; no dynamic allocation allowed)
// ---------------------------------------------------------------------------
__device__ float g_xn  [8 * 512 * 1024];   // GroupNorm output          16 MB
__device__ float g_qkv [8 * 1536 * 1024];  // QKV projection            48 MB
__device__ float g_qt  [64 * 1024 * 64];   // Q^T (scaled, tf32) [bh][i][c]
__device__ float g_kt  [64 * 1024 * 64];   // K^T (tf32) [bh][j][c]
__device__ float g_wv  [8 * 512 * 1024];   // attention out (flat view) 16 MB

__device__ __forceinline__ float to_tf32(float x) {
    float y; asm("cvt.rna.tf32.f32 %0, %1;" : "=f"(y) : "f"(x)); return y;
}
__device__ __forceinline__ void mma_tf32_16x8x8(
    float& d0, float& d1, float& d2, float& d3,
    uint32_t a0, uint32_t a1, uint32_t a2, uint32_t a3,
    uint32_t b0, uint32_t b1) {
    asm volatile(
        "mma.sync.aligned.m16n8k8.row.col.f32.tf32.tf32.f32 "
        "{%0,%1,%2,%3}, {%4,%5,%6,%7}, {%8,%9}, {%0,%1,%2,%3};"
        : "+f"(d0), "+f"(d1), "+f"(d2), "+f"(d3)
        : "r"(a0), "r"(a1), "r"(a2), "r"(a3), "r"(b0), "r"(b1));
}
__device__ __forceinline__ void ldsm_x4(uint32_t& r0, uint32_t& r1,
                                        uint32_t& r2, uint32_t& r3,
                                        uint32_t addr) {
    asm volatile("ldmatrix.sync.aligned.m8n8.x4.shared.b16 {%0,%1,%2,%3}, [%4];"
                 : "=r"(r0), "=r"(r1), "=r"(r2), "=r"(r3) : "r"(addr));
}
__device__ __forceinline__ uint32_t smem_u32(const void* p) {
    uint32_t a;
    asm("{ .reg .u64 t; cvta.to.shared.u64 t, %1; cvt.u32.u64 %0, t; }"
        : "=r"(a) : "l"(p));
    return a;
}

// ---------------------------------------------------------------------------
// GroupNorm
// ---------------------------------------------------------------------------
__global__ void gn_kernel(const float* __restrict__ x,
                          const float* __restrict__ gw,
                          const float* __restrict__ gb) {
    const int g = blockIdx.x, n = blockIdx.y;
    const float* xp = x + ((size_t)n * 512 + (size_t)g * 16) * 1024;
    float s = 0.f, s2 = 0.f;
    for (int i = threadIdx.x; i < 16384; i += 256) {
        float v = xp[i]; s += v; s2 += v * v;
    }
    __shared__ float rs[8], rs2[8];
#pragma unroll
    for (int o = 16; o; o >>= 1) {
        s  += __shfl_xor_sync(0xffffffffu, s,  o);
        s2 += __shfl_xor_sync(0xffffffffu, s2, o);
    }
    const int wid = threadIdx.x >> 5, lane = threadIdx.x & 31;
    if (lane == 0) { rs[wid] = s; rs2[wid] = s2; }
    __syncthreads();
    if (threadIdx.x < 32) {
        s  = (threadIdx.x < 8) ? rs [threadIdx.x] : 0.f;
        s2 = (threadIdx.x < 8) ? rs2[threadIdx.x] : 0.f;
#pragma unroll
        for (int o = 4; o; o >>= 1) {
            s  += __shfl_xor_sync(0xffffffffu, s,  o);
            s2 += __shfl_xor_sync(0xffffffffu, s2, o);
        }
        if (threadIdx.x == 0) { rs[0] = s; rs2[0] = s2; }
    }
    __syncthreads();
    const float mean = rs[0] * (1.f / 16384.f);
    const float var  = rs2[0] * (1.f / 16384.f) - mean * mean;
    const float rstd = rsqrtf(var + 1e-5f);
    float* op = g_xn + ((size_t)n * 512 + (size_t)g * 16) * 1024;
    for (int i = threadIdx.x; i < 16384; i += 256) {
        const int ch = g * 16 + (i >> 10);
        op[i] = (xp[i] - mean) * rstd * gw[ch] + gb[ch];
    }
}

// ---------------------------------------------------------------------------
// tf32 mma.sync GEMM:  Y[nb][m][n] = sum_k W[m][k] * B[nb][k][n] + bias[m]
// ---------------------------------------------------------------------------
__global__ __launch_bounds__(256)
void mma_gemm(const float* __restrict__ W, const float* __restrict__ bias,
              const float* __restrict__ B, float* __restrict__ Y, int M) {
    __shared__ float As[128 * 36];   // [m][k]
    __shared__ float Bs[32 * 136];   // [k][n]

    const int tid = threadIdx.x, w = tid >> 5, lane = tid & 31;
    const int n0 = blockIdx.x * 128, m0 = blockIdx.y * 128, nb = blockIdx.z;
    const float* Bb = B + (size_t)nb * 512 * 1024;
    float* Yb = Y + (size_t)nb * M * 1024;

    const int wm = (w >> 2) * 64;
    const int wn = (w & 3) * 32;
    const int gid = lane >> 2;
    const int tig = lane & 3;

    float acc[4][4][4] = {};

    float4 pa[4], pb[4];
#pragma unroll
    for (int v = 0; v < 4; v++) {
        const int fa = tid + 256 * v;
        pa[v] = *(const float4*)&W [(size_t)(m0 + (fa >> 3)) * 512 + (fa & 7) * 4];
        const int fb = tid + 256 * v;
        pb[v] = *(const float4*)&Bb[(size_t)(fb >> 5) * 1024 + n0 + (fb & 31) * 4];
    }

    for (int kc = 0; kc < 16; kc++) {
        __syncthreads();
#pragma unroll
        for (int v = 0; v < 4; v++) {
            const int fa = tid + 256 * v;
            float4 a = pa[v];
            a.x = to_tf32(a.x); a.y = to_tf32(a.y); a.z = to_tf32(a.z); a.w = to_tf32(a.w);
            *(float4*)&As[(fa >> 3) * 36 + (fa & 7) * 4] = a;
            const int fb = tid + 256 * v;
            float4 b = pb[v];
            b.x = to_tf32(b.x); b.y = to_tf32(b.y); b.z = to_tf32(b.z); b.w = to_tf32(b.w);
            *(float4*)&Bs[(fb >> 5) * 136 + (fb & 31) * 4] = b;
        }
        __syncthreads();

        if (kc < 15) {
            const int k0 = (kc + 1) * 32;
#pragma unroll
            for (int v = 0; v < 4; v++) {
                const int fa = tid + 256 * v;
                pa[v] = *(const float4*)&W [(size_t)(m0 + (fa >> 3)) * 512 + k0 + (fa & 7) * 4];
                const int fb = tid + 256 * v;
                pb[v] = *(const float4*)&Bb[(size_t)(k0 + (fb >> 5)) * 1024 + n0 + (fb & 31) * 4];
            }
        }

#pragma unroll
        for (int ks = 0; ks < 4; ks++) {
            const int kk = ks * 8;
            uint32_t af[4][4];
#pragma unroll
            for (int mt = 0; mt < 4; mt++) {
                const int r = (wm + mt * 16 + gid) * 36 + kk + tig;
                af[mt][0] = __float_as_uint(As[r]);
                af[mt][1] = __float_as_uint(As[r + 8 * 36]);
                af[mt][2] = __float_as_uint(As[r + 4]);
                af[mt][3] = __float_as_uint(As[r + 8 * 36 + 4]);
            }
            uint32_t bf[4][2];
#pragma unroll
            for (int nt = 0; nt < 4; nt++) {
                const int c = (kk + tig) * 136 + wn + nt * 8 + gid;
                bf[nt][0] = __float_as_uint(Bs[c]);
                bf[nt][1] = __float_as_uint(Bs[c + 4 * 136]);
            }
#pragma unroll
            for (int mt = 0; mt < 4; mt++)
#pragma unroll
                for (int nt = 0; nt < 4; nt++)
                    mma_tf32_16x8x8(acc[mt][nt][0], acc[mt][nt][1],
                                    acc[mt][nt][2], acc[mt][nt][3],
                                    af[mt][0], af[mt][1], af[mt][2], af[mt][3],
                                    bf[nt][0], bf[nt][1]);
        }
    }

#pragma unroll
    for (int mt = 0; mt < 4; mt++) {
        const int r0 = m0 + wm + mt * 16 + gid;
        const float bv0 = bias[r0], bv1 = bias[r0 + 8];
#pragma unroll
        for (int nt = 0; nt < 4; nt++) {
            const int col = n0 + wn + nt * 8 + tig * 2;
            *(float2*)&Yb[(size_t)r0 * 1024 + col] =
                make_float2(acc[mt][nt][0] + bv0, acc[mt][nt][1] + bv0);
            *(float2*)&Yb[(size_t)(r0 + 8) * 1024 + col] =
                make_float2(acc[mt][nt][2] + bv1, acc[mt][nt][3] + bv1);
        }
    }
}

// ---------------------------------------------------------------------------
// Q/K transpose: qkv section [c][pos] -> [bh][pos][c] fp32, tf32-rounded.
// Q gets the 1/8 softmax scale folded in before rounding.
// grid (32 pos-tiles, 2 c-tiles, 128 = bh*2 + {0=Q,1=K}), block (32, 8)
// ---------------------------------------------------------------------------
__global__ void qktrans_kernel() {
    __shared__ float t[32][33];
    const int qk = blockIdx.z & 1;
    const int bh = blockIdx.z >> 1;
    const int n = bh >> 3, head = bh & 7;
    const float* src = g_qkv +
        ((size_t)n * 1536 + (qk ? 512 : 0) + (size_t)head * 64) * 1024;
    float* dst = (qk ? g_kt : g_qt) + (size_t)bh * 65536;
    const float scale = qk ? 1.0f : 0.125f;
    const int j0 = blockIdx.x * 32, c0 = blockIdx.y * 32;
    for (int r = threadIdx.y; r < 32; r += 8)
        t[r][threadIdx.x] = src[(size_t)(c0 + r) * 1024 + j0 + threadIdx.x];
    __syncthreads();
    for (int r = threadIdx.y; r < 32; r += 8)
        dst[(size_t)(j0 + r) * 64 + c0 + threadIdx.x] =
            to_tf32(t[threadIdx.x][r] * scale);
}

// ---------------------------------------------------------------------------
// tf32 tensor-core flash attention with ldmatrix fragment loads.
// grid(16 i-tiles, 64 bh), block 128 (4 warps); warp w owns i-rows w*16..+15.
// QK^T: A = Qt frags (regs, loaded once), B = Kt staged [j][c].
// PV:   A = P [i][j] (smem, warp-private rows), B = V native [c][j].
// All tiles stride 68 floats (17 x 16B, odd -> ldmatrix conflict-free).
// ---------------------------------------------------------------------------
#define ASTR 68
#define ATTN_SMEM (3 * 64 * ASTR * 4)   // 52224 B

__global__ __launch_bounds__(128)
void attn_tc_kernel() {
    extern __shared__ float sm[];
    float* Ks = sm;                 // [j][c]
    float* Vs = sm + 64 * ASTR;     // [c][j]
    float* Ps = sm + 128 * ASTR;    // [i][j]

    const int tid = threadIdx.x;
    const int w = tid >> 5, lane = tid & 31;
    const int gid = lane >> 2, tig = lane & 3;
    const int wm = w * 16;
    const int bh = blockIdx.y, n = bh >> 3, head = bh & 7;
    const int i0 = blockIdx.x * 64;

    const float* qt = g_qt + (size_t)bh * 65536;                        // [i][c]
    const float* kt = g_kt + (size_t)bh * 65536;                        // [j][c]
    const float* vg = g_qkv + ((size_t)n * 1536 + 1024 + (size_t)head * 64) * 1024; // [c][j]

    // ldmatrix per-thread row addresses
    const int lane7 = lane & 7, laneq = lane >> 3;
    const uint32_t KsU = smem_u32(Ks), VsU = smem_u32(Vs), PsU = smem_u32(Ps);
    const uint32_t aK = KsU + (uint32_t)(lane7 * ASTR + laneq * 4) * 4;
    const uint32_t aV = VsU + (uint32_t)(lane7 * ASTR + laneq * 4) * 4;
    const uint32_t aP = PsU +
        (uint32_t)((wm + lane7 + ((laneq & 1) << 3)) * ASTR + (lane >> 4) * 4) * 4;

    // Q fragments (scaled + tf32-rounded already), loaded once from gmem
    uint32_t qf[8][4];
#pragma unroll
    for (int ks = 0; ks < 8; ks++) {
        const size_t r0 = (size_t)(i0 + wm + gid) * 64 + ks * 8 + tig;
        qf[ks][0] = __float_as_uint(qt[r0]);
        qf[ks][1] = __float_as_uint(qt[r0 + 8 * 64]);
        qf[ks][2] = __float_as_uint(qt[r0 + 4]);
        qf[ks][3] = __float_as_uint(qt[r0 + 8 * 64 + 4]);
    }

    float oacc[8][4] = {};
    float m0 = -1e30f, m1 = -1e30f, l0 = 0.f, l1 = 0.f;

    for (int jt = 0; jt < 16; jt++) {
        const int j0 = jt * 64;
        __syncthreads();
        // Stage K tile [j][c] (pre-rounded) and V tile [c][j] (round here)
#pragma unroll
        for (int v = 0; v < 8; v++) {
            const int f = tid + 128 * v;          // 0..1023 float4s
            const int r = f >> 4, c4 = (f & 15) * 4;
            *(float4*)&Ks[r * ASTR + c4] =
                *(const float4*)&kt[(size_t)(j0 + r) * 64 + c4];
            float4 vv = *(const float4*)&vg[(size_t)r * 1024 + j0 + c4];
            vv.x = to_tf32(vv.x); vv.y = to_tf32(vv.y);
            vv.z = to_tf32(vv.z); vv.w = to_tf32(vv.w);
            *(float4*)&Vs[r * ASTR + c4] = vv;
        }
        __syncthreads();

        // S = Q K^T  (per warp m16 x n64); B-frags via ldmatrix from Ks[j][c]
        float sacc[8][4] = {};
#pragma unroll
        for (int nt = 0; nt < 8; nt++) {
            uint32_t kb[16];
#pragma unroll
            for (int cg = 0; cg < 4; cg++)
                ldsm_x4(kb[4 * cg], kb[4 * cg + 1], kb[4 * cg + 2], kb[4 * cg + 3],
                        aK + nt * (8 * ASTR * 4) + cg * 64);
#pragma unroll
            for (int ks = 0; ks < 8; ks++)
                mma_tf32_16x8x8(sacc[nt][0], sacc[nt][1], sacc[nt][2], sacc[nt][3],
                                qf[ks][0], qf[ks][1], qf[ks][2], qf[ks][3],
                                kb[2 * ks], kb[2 * ks + 1]);
        }

        // Online softmax (rows gid / gid+8, spread across the quad)
        float tm0 = -1e30f, tm1 = -1e30f;
#pragma unroll
        for (int nt = 0; nt < 8; nt++) {
            tm0 = fmaxf(tm0, fmaxf(sacc[nt][0], sacc[nt][1]));
            tm1 = fmaxf(tm1, fmaxf(sacc[nt][2], sacc[nt][3]));
        }
        tm0 = fmaxf(tm0, __shfl_xor_sync(0xffffffffu, tm0, 1));
        tm0 = fmaxf(tm0, __shfl_xor_sync(0xffffffffu, tm0, 2));
        tm1 = fmaxf(tm1, __shfl_xor_sync(0xffffffffu, tm1, 1));
        tm1 = fmaxf(tm1, __shfl_xor_sync(0xffffffffu, tm1, 2));
        const float mn0 = fmaxf(m0, tm0), mn1 = fmaxf(m1, tm1);
        const float c0 = __expf(m0 - mn0), c1 = __expf(m1 - mn1);
        m0 = mn0; m1 = mn1;
        float s0 = 0.f, s1 = 0.f;
#pragma unroll
        for (int nt = 0; nt < 8; nt++) {
            sacc[nt][0] = __expf(sacc[nt][0] - m0); s0 += sacc[nt][0];
            sacc[nt][1] = __expf(sacc[nt][1] - m0); s0 += sacc[nt][1];
            sacc[nt][2] = __expf(sacc[nt][2] - m1); s1 += sacc[nt][2];
            sacc[nt][3] = __expf(sacc[nt][3] - m1); s1 += sacc[nt][3];
        }
        s0 += __shfl_xor_sync(0xffffffffu, s0, 1);
        s0 += __shfl_xor_sync(0xffffffffu, s0, 2);
        s1 += __shfl_xor_sync(0xffffffffu, s1, 1);
        s1 += __shfl_xor_sync(0xffffffffu, s1, 2);
        l0 = l0 * c0 + s0;
        l1 = l1 * c1 + s1;
#pragma unroll
        for (int nt = 0; nt < 8; nt++) {
            oacc[nt][0] *= c0; oacc[nt][1] *= c0;
            oacc[nt][2] *= c1; oacc[nt][3] *= c1;
        }

        // Store P (tf32-rounded) to warp-private rows of Ps
        float* pr0 = &Ps[(wm + gid) * ASTR];
        float* pr1 = &Ps[(wm + gid + 8) * ASTR];
#pragma unroll
        for (int nt = 0; nt < 8; nt++) {
            const int col = nt * 8 + tig * 2;
            *(float2*)&pr0[col] = make_float2(to_tf32(sacc[nt][0]), to_tf32(sacc[nt][1]));
            *(float2*)&pr1[col] = make_float2(to_tf32(sacc[nt][2]), to_tf32(sacc[nt][3]));
        }
        __syncwarp();

        // PV: A = P via ldmatrix (warp-private), B = Vs[c][j] via ldmatrix
        uint32_t pa[8][4];
#pragma unroll
        for (int ks = 0; ks < 8; ks++)
            ldsm_x4(pa[ks][0], pa[ks][1], pa[ks][2], pa[ks][3], aP + ks * 32);
#pragma unroll
        for (int nt = 0; nt < 8; nt++) {
            uint32_t vb[16];
#pragma unroll
            for (int cg = 0; cg < 4; cg++)
                ldsm_x4(vb[4 * cg], vb[4 * cg + 1], vb[4 * cg + 2], vb[4 * cg + 3],
                        aV + nt * (8 * ASTR * 4) + cg * 64);
#pragma unroll
            for (int ks = 0; ks < 8; ks++)
                mma_tf32_16x8x8(oacc[nt][0], oacc[nt][1], oacc[nt][2], oacc[nt][3],
                                pa[ks][0], pa[ks][1], pa[ks][2], pa[ks][3],
                                vb[2 * ks], vb[2 * ks + 1]);
        }
    }

    // Epilogue: normalize, store to torch-faithful flat layout
    const float inv0 = 1.f / l0, inv1 = 1.f / l1;
    float* wb = g_wv + (size_t)n * 524288 + (size_t)head * 65536;
    const int row0 = i0 + wm + gid, row1 = row0 + 8;
#pragma unroll
    for (int nt = 0; nt < 8; nt++) {
        const int col = nt * 8 + tig * 2;
        *(float2*)&wb[(size_t)row0 * 64 + col] =
            make_float2(oacc[nt][0] * inv0, oacc[nt][1] * inv0);
        *(float2*)&wb[(size_t)row1 * 64 + col] =
            make_float2(oacc[nt][2] * inv1, oacc[nt][3] * inv1);
    }
}

// ---------------------------------------------------------------------------
// Launch
// ---------------------------------------------------------------------------
extern "C" void kernel_launch(void* const* d_in, const int* in_sizes, int n_in,
                              void* d_out, int out_size) {
    const float* x     = (const float*)d_in[0];
    const float* gw    = (const float*)d_in[1];
    const float* gb    = (const float*)d_in[2];
    const float* qkv_w = (const float*)d_in[3];
    const float* qkv_b = (const float*)d_in[4];
    const float* out_w = (const float*)d_in[5];
    const float* out_b = (const float*)d_in[6];
    float* out = (float*)d_out;

    float *xn_p, *qkv_p, *wv_p;
    cudaGetSymbolAddress((void**)&xn_p,  g_xn);
    cudaGetSymbolAddress((void**)&qkv_p, g_qkv);
    cudaGetSymbolAddress((void**)&wv_p,  g_wv);

    cudaFuncSetAttribute(attn_tc_kernel,
                         cudaFuncAttributeMaxDynamicSharedMemorySize, ATTN_SMEM);

    gn_kernel<<<dim3(32, 8), 256>>>(x, gw, gb);
    mma_gemm<<<dim3(8, 12, 8), 256>>>(qkv_w, qkv_b, xn_p, qkv_p, 1536);
    qktrans_kernel<<<dim3(32, 2, 128), dim3(32, 8)>>>();
    attn_tc_kernel<<<dim3(16, 64), 128, ATTN_SMEM>>>();
    mma_gemm<<<dim3(8, 4, 8), 256>>>(out_w, out_b, wv_p, out, 512);
}